// round 16
// baseline (speedup 1.0000x reference)
#include <cuda_runtime.h>
#include <cstdint>

#define N_NODES 65536
#define NODE_MASK 0xFFFF
#define DIM 128
#define E_EDGES 1048576
#define TOT_EDGES (E_EDGES + N_NODES)

// ---- static device scratch (no allocations allowed) ----
__device__ float g_xl[N_NODES * DIM];                      // 32 MB: x @ W_l
__device__ float g_xr[N_NODES * DIM];                      // 32 MB: x @ W_r
__device__ __align__(16) int g_cnt[N_NODES];
__device__ __align__(16) int g_off[N_NODES + 4];
__device__ __align__(16) int g_cur[N_NODES];
__device__ int   g_srt[TOT_EDGES];
__device__ int   g_is64;

// ---- f32x2 packed-FMA helpers (FFMA2 — only reachable via PTX) ----
__device__ __forceinline__ unsigned long long dupf(float f) {
    unsigned long long r;
    asm("mov.b64 %0,{%1,%1};" : "=l"(r) : "f"(f));
    return r;
}
__device__ __forceinline__ void ffma2(unsigned long long& d,
                                      unsigned long long a, unsigned long long b) {
    asm("fma.rn.f32x2 %0,%1,%2,%0;" : "+l"(d) : "l"(a), "l"(b));
}
__device__ __forceinline__ float2 unpk(unsigned long long v) {
    float2 r;
    asm("mov.b64 {%0,%1},%2;" : "=f"(r.x), "=f"(r.y) : "l"(v));
    return r;
}

// ---------------------------------------------------------------------------
// Fused detect + zero.
__global__ void k_detect_zero(const unsigned int* __restrict__ w) {
    int i = blockIdx.x * blockDim.x + threadIdx.x;
    if (i < N_NODES) g_cnt[i] = 0;
    if (blockIdx.x == 0) {
        __shared__ unsigned int red[256];
        unsigned int v = w[2 * threadIdx.x + 1] | w[2 * (threadIdx.x + 256) + 1] |
                         w[2 * (threadIdx.x + 512) + 1] | w[2 * (threadIdx.x + 768) + 1];
        red[threadIdx.x] = v;
        __syncthreads();
        for (int s = 128; s > 0; s >>= 1) {
            if (threadIdx.x < s) red[threadIdx.x] |= red[threadIdx.x + s];
            __syncthreads();
        }
        if (threadIdx.x == 0) g_is64 = (red[0] == 0u) ? 1 : 0;
    }
}

__device__ __forceinline__ int edge_at(const int* __restrict__ ei, int pos, int is64) {
    return (is64 ? ei[2 * pos] : ei[pos]) & NODE_MASK;
}

__global__ void k_hist(const int* __restrict__ ei) {
    int i = blockIdx.x * blockDim.x + threadIdx.x;
    int is64 = g_is64;
    if (i < E_EDGES) {
        int d = edge_at(ei, E_EDGES + i, is64);
        atomicAdd(&g_cnt[d], 1);
    }
}

__global__ __launch_bounds__(1024) void k_scan() {
    __shared__ int part[1024];
    int tid  = threadIdx.x;
    int base = tid * 64;
    const int4* cp = (const int4*)(g_cnt + base);
    int sum = 0;
#pragma unroll
    for (int i = 0; i < 16; i++) {
        int4 c = cp[i];
        sum += c.x + c.y + c.z + c.w + 4;
    }
    part[tid] = sum;
    __syncthreads();
    for (int s = 1; s < 1024; s <<= 1) {
        int v = (tid >= s) ? part[tid - s] : 0;
        __syncthreads();
        part[tid] += v;
        __syncthreads();
    }
    int run = part[tid] - sum;
    int4* op = (int4*)(g_off + base);
    int4* up = (int4*)(g_cur + base);
#pragma unroll
    for (int i = 0; i < 16; i++) {
        int4 c = cp[i];
        int4 o;
        o.x = run; run += c.x + 1;
        o.y = run; run += c.y + 1;
        o.z = run; run += c.z + 1;
        o.w = run; run += c.w + 1;
        op[i] = o; up[i] = o;
    }
    if (tid == 1023) g_off[N_NODES] = run;
}

__global__ void k_scatter(const int* __restrict__ ei) {
    int i = blockIdx.x * blockDim.x + threadIdx.x;
    if (i >= TOT_EDGES) return;
    int is64 = g_is64;
    int s, d;
    if (i < E_EDGES) {
        s = edge_at(ei, i, is64);
        d = edge_at(ei, E_EDGES + i, is64);
    } else {
        s = d = i - E_EDGES;
    }
    int pos = atomicAdd(&g_cur[d], 1);
    g_srt[pos] = s;
}

// ---------------------------------------------------------------------------
// GEMM with packed f32x2 FMAs, double-buffered smem pipeline (R13, 88us).
__global__ __launch_bounds__(256, 3) void k_gemm(const float* __restrict__ x,
                                                 const float* __restrict__ Wl,
                                                 const float* __restrict__ Wr) {
    __shared__ float xs[2][16][68];
    __shared__ float ws[2][16][128];

    const float* W    = blockIdx.y ? Wr : Wl;
    float*       outp = blockIdx.y ? g_xr : g_xl;

    int tid  = threadIdx.x;
    int row0 = blockIdx.x * 64;
    int rowg = tid >> 5;
    int colg = tid & 31;

    unsigned long long acc[4][4];
#pragma unroll
    for (int p = 0; p < 4; p++)
#pragma unroll
        for (int j = 0; j < 4; j++) acc[p][j] = 0ULL;

    int lm = tid >> 2;
    int lk = (tid & 3) * 4;
    int wk = tid >> 5;
    int wc = (tid & 31) * 4;

    const float* xrow = x + (size_t)(row0 + lm) * DIM + lk;
    const float* wp   = W + (size_t)wk * DIM + wc;

    float4 xv  = *(const float4*)(xrow);
    float4 wv0 = *(const float4*)(wp);
    float4 wv1 = *(const float4*)(wp + 8 * DIM);
    xs[0][lk + 0][lm] = xv.x;
    xs[0][lk + 1][lm] = xv.y;
    xs[0][lk + 2][lm] = xv.z;
    xs[0][lk + 3][lm] = xv.w;
    *(float4*)&ws[0][wk][wc]     = wv0;
    *(float4*)&ws[0][wk + 8][wc] = wv1;
    __syncthreads();

    for (int kt = 0; kt < 8; kt++) {
        int b = kt & 1;
        if (kt < 7) {
            xv  = *(const float4*)(xrow + (kt + 1) * 16);
            wv0 = *(const float4*)(wp + (size_t)(kt + 1) * 16 * DIM);
            wv1 = *(const float4*)(wp + (size_t)(kt + 1) * 16 * DIM + 8 * DIM);
        }
#pragma unroll
        for (int k = 0; k < 16; k++) {
            ulonglong2 a01 = *(const ulonglong2*)&xs[b][k][rowg * 8];
            ulonglong2 a23 = *(const ulonglong2*)&xs[b][k][rowg * 8 + 4];
            unsigned long long xp[4] = {a01.x, a01.y, a23.x, a23.y};
            float4 w4 = *(const float4*)&ws[b][k][colg * 4];
            unsigned long long wd[4] = {dupf(w4.x), dupf(w4.y), dupf(w4.z), dupf(w4.w)};
#pragma unroll
            for (int p = 0; p < 4; p++)
#pragma unroll
                for (int j = 0; j < 4; j++)
                    ffma2(acc[p][j], xp[p], wd[j]);
        }
        __syncthreads();
        if (kt < 7) {
            int nb = b ^ 1;
            xs[nb][lk + 0][lm] = xv.x;
            xs[nb][lk + 1][lm] = xv.y;
            xs[nb][lk + 2][lm] = xv.z;
            xs[nb][lk + 3][lm] = xv.w;
            *(float4*)&ws[nb][wk][wc]     = wv0;
            *(float4*)&ws[nb][wk + 8][wc] = wv1;
            __syncthreads();
        }
    }

#pragma unroll
    for (int p = 0; p < 4; p++) {
        float2 c0 = unpk(acc[p][0]);
        float2 c1 = unpk(acc[p][1]);
        float2 c2 = unpk(acc[p][2]);
        float2 c3 = unpk(acc[p][3]);
        size_t ra = row0 + rowg * 8 + 2 * p;
        *(float4*)(outp + ra * DIM + colg * 4)       = make_float4(c0.x, c1.x, c2.x, c3.x);
        *(float4*)(outp + (ra + 1) * DIM + colg * 4) = make_float4(c0.y, c1.y, c2.y, c3.y);
    }
}

// ---------------------------------------------------------------------------
// Fused GATv2 attention + aggregation. TWO warps per destination node, each
// handling half the edge list with the proven 4-way unroll; partial (den,acc)
// merged through smem (exact: no max-rescaling anywhere).
#define NEG_SLOPE 0.2f
__device__ __forceinline__ float edge_score(float4 v, float4 xr4,
                                            float4 a06, float4 a04) {
    float zx = v.x + xr4.x, zy = v.y + xr4.y;
    float zz = v.z + xr4.z, zw = v.w + xr4.w;
    float t = fmaf(a06.x, zx, a04.x * fabsf(zx));
    t = fmaf(a06.y, zy, fmaf(a04.y, fabsf(zy), t));
    t = fmaf(a06.z, zz, fmaf(a04.z, fabsf(zz), t));
    t = fmaf(a06.w, zw, fmaf(a04.w, fabsf(zw), t));
    return t;
}
__device__ __forceinline__ float head_sum(float p) {
    p += __shfl_xor_sync(0xffffffffu, p, 1);
    p += __shfl_xor_sync(0xffffffffu, p, 2);
    p += __shfl_xor_sync(0xffffffffu, p, 4);
    p += __shfl_xor_sync(0xffffffffu, p, 8);
    return p;
}

__global__ __launch_bounds__(256) void k_attn(const float* __restrict__ att,
                                              const float* __restrict__ bias,
                                              float* __restrict__ out) {
    __shared__ float s_par[4][32][5];   // [node][lane][acc4 + den]; 5 coprime 32

    int tid   = threadIdx.x;
    int wpair = tid >> 6;               // 0..3: node within block
    int half  = (tid >> 5) & 1;         // which half of the edge list
    int lane  = tid & 31;
    int gw    = blockIdx.x * 4 + wpair; // grid sized so gw < N_NODES always

    const float4 xr4 = *(const float4*)(g_xr + (size_t)gw * DIM + lane * 4);
    const float4 a4  = *(const float4*)(att + lane * 4);
    float4 a06 = make_float4(0.6f * a4.x, 0.6f * a4.y, 0.6f * a4.z, 0.6f * a4.w);
    float4 a04 = make_float4(0.4f * a4.x, 0.4f * a4.y, 0.4f * a4.z, 0.4f * a4.w);

    int beg = g_off[gw];
    int end = g_off[gw + 1];
    int mid = beg + ((end - beg + 1) >> 1);
    int b0  = half ? mid : beg;
    int e0  = half ? end : mid;

    float  den0 = 0.f, den1 = 0.f;
    float4 acc0 = make_float4(0.f, 0.f, 0.f, 0.f);
    float4 acc1 = make_float4(0.f, 0.f, 0.f, 0.f);

    int myidx = (b0 + lane < e0) ? g_srt[b0 + lane] : 0;

    for (int base = b0; base < e0; base += 32) {
        int nrem = e0 - base;
        int cnt  = nrem < 32 ? nrem : 32;
        int cur  = myidx;
        int nb = base + 32;
        myidx = (nb + lane < e0) ? g_srt[nb + lane] : 0;

        int j = 0;
        for (; j + 4 <= cnt; j += 4) {
            int s0 = __shfl_sync(0xffffffffu, cur, j);
            int s1 = __shfl_sync(0xffffffffu, cur, j + 1);
            int s2 = __shfl_sync(0xffffffffu, cur, j + 2);
            int s3 = __shfl_sync(0xffffffffu, cur, j + 3);
            float4 v0 = *(const float4*)(g_xl + (size_t)s0 * DIM + lane * 4);
            float4 v1 = *(const float4*)(g_xl + (size_t)s1 * DIM + lane * 4);
            float4 v2 = *(const float4*)(g_xl + (size_t)s2 * DIM + lane * 4);
            float4 v3 = *(const float4*)(g_xl + (size_t)s3 * DIM + lane * 4);
            float p0 = head_sum(edge_score(v0, xr4, a06, a04));
            float p1 = head_sum(edge_score(v1, xr4, a06, a04));
            float p2 = head_sum(edge_score(v2, xr4, a06, a04));
            float p3 = head_sum(edge_score(v3, xr4, a06, a04));
            float w0 = __expf(p0), w1 = __expf(p1), w2 = __expf(p2), w3 = __expf(p3);
            den0 += w0 + w2;
            den1 += w1 + w3;
            acc0.x = fmaf(w0, v0.x, fmaf(w2, v2.x, acc0.x));
            acc0.y = fmaf(w0, v0.y, fmaf(w2, v2.y, acc0.y));
            acc0.z = fmaf(w0, v0.z, fmaf(w2, v2.z, acc0.z));
            acc0.w = fmaf(w0, v0.w, fmaf(w2, v2.w, acc0.w));
            acc1.x = fmaf(w1, v1.x, fmaf(w3, v3.x, acc1.x));
            acc1.y = fmaf(w1, v1.y, fmaf(w3, v3.y, acc1.y));
            acc1.z = fmaf(w1, v1.z, fmaf(w3, v3.z, acc1.z));
            acc1.w = fmaf(w1, v1.w, fmaf(w3, v3.w, acc1.w));
        }
        for (; j < cnt; j++) {
            int s = __shfl_sync(0xffffffffu, cur, j);
            float4 v = *(const float4*)(g_xl + (size_t)s * DIM + lane * 4);
            float w = __expf(head_sum(edge_score(v, xr4, a06, a04)));
            den0 += w;
            acc0.x = fmaf(w, v.x, acc0.x);
            acc0.y = fmaf(w, v.y, acc0.y);
            acc0.z = fmaf(w, v.z, acc0.z);
            acc0.w = fmaf(w, v.w, acc0.w);
        }
    }

    float  den = den0 + den1;
    float4 acc = make_float4(acc0.x + acc1.x, acc0.y + acc1.y,
                             acc0.z + acc1.z, acc0.w + acc1.w);

    if (half) {
        s_par[wpair][lane][0] = acc.x;
        s_par[wpair][lane][1] = acc.y;
        s_par[wpair][lane][2] = acc.z;
        s_par[wpair][lane][3] = acc.w;
        s_par[wpair][lane][4] = den;
    }
    __syncthreads();
    if (!half) {
        acc.x += s_par[wpair][lane][0];
        acc.y += s_par[wpair][lane][1];
        acc.z += s_par[wpair][lane][2];
        acc.w += s_par[wpair][lane][3];
        den   += s_par[wpair][lane][4];

        float inv = 1.f / den;
        float4 b4 = *(const float4*)(bias + lane * 4);
        float4 o;
        o.x = fmaf(acc.x, inv, b4.x);
        o.y = fmaf(acc.y, inv, b4.y);
        o.z = fmaf(acc.z, inv, b4.z);
        o.w = fmaf(acc.w, inv, b4.w);
        *(float4*)(out + (size_t)gw * DIM + lane * 4) = o;
    }
}

// ---------------------------------------------------------------------------
extern "C" void kernel_launch(void* const* d_in, const int* in_sizes, int n_in,
                              void* d_out, int out_size) {
    const float* x    = 0;
    const int*   ei   = 0;
    const float* Wl   = 0;
    const float* Wr   = 0;
    const float* att  = 0;
    const float* bias = 0;
    for (int i = 0; i < n_in; i++) {
        int sz = in_sizes[i];
        if (sz == 8388608)                      x  = (const float*)d_in[i];
        else if (sz == 2097152 || sz == 4194304) ei = (const int*)d_in[i];
        else if (sz == 16384) { if (!Wl) Wl = (const float*)d_in[i]; else Wr = (const float*)d_in[i]; }
        else if (sz == 128)   { if (!att) att = (const float*)d_in[i]; else bias = (const float*)d_in[i]; }
    }
    float* out = (float*)d_out;

    k_detect_zero<<<N_NODES / 256, 256>>>((const unsigned int*)ei);  // 0
    k_hist<<<E_EDGES / 256, 256>>>(ei);                              // 1
    k_scan<<<1, 1024>>>();                                           // 2
    k_scatter<<<(TOT_EDGES + 255) / 256, 256>>>(ei);                 // 3  <- profiled
    k_gemm<<<dim3(N_NODES / 64, 2), 256>>>(x, Wl, Wr);               // 4
    k_attn<<<N_NODES / 4, 256>>>(att, bias, out);                    // 5
}

// round 17
// speedup vs baseline: 1.0627x; 1.0627x over previous
#include <cuda_runtime.h>
#include <cstdint>

#define N_NODES 65536
#define NODE_MASK 0xFFFF
#define DIM 128
#define E_EDGES 1048576
#define TOT_EDGES (E_EDGES + N_NODES)

// ---- static device scratch (no allocations allowed) ----
__device__ float g_xl[N_NODES * DIM];                      // 32 MB: x @ W_l
__device__ float g_xr[N_NODES * DIM];                      // 32 MB: x @ W_r
__device__ __align__(16) int g_cnt[N_NODES];
__device__ __align__(16) int g_off[N_NODES + 4];
__device__ __align__(16) int g_cur[N_NODES];
__device__ int   g_srt[TOT_EDGES];
__device__ int   g_is64;
// fragment-packed bf16 W: [mat][kstep][breg][lane][ntile] (8192 per mat)
__device__ __align__(16) uint32_t g_bh[16384];
__device__ __align__(16) uint32_t g_bl[16384];

// ---------------------------------------------------------------------------
__device__ __forceinline__ uint32_t pack_hi(float a, float b) {
    // truncated bf16 pair: low half = bf16(a), high = bf16(b)
    return __byte_perm(__float_as_uint(a), __float_as_uint(b), 0x7632);
}
__device__ __forceinline__ uint32_t pack_rn(float lo_el, float hi_el) {
    uint32_t r;  // d.hi = bf16(first src), d.lo = bf16(second src)
    asm("cvt.rn.bf16x2.f32 %0,%1,%2;" : "=r"(r) : "f"(hi_el), "f"(lo_el));
    return r;
}
__device__ __forceinline__ float trunc_res(float f) {
    return f - __uint_as_float(__float_as_uint(f) & 0xFFFF0000u);
}

// Prep: pack W_l/W_r into mma.sync B-fragment order, bf16 hi/lo split.
__global__ void k_prep(const float* __restrict__ Wl, const float* __restrict__ Wr) {
    int idx = blockIdx.x * blockDim.x + threadIdx.x;   // 0..16383
    int nt   = idx & 15;
    int lane = (idx >> 4) & 31;
    int b    = (idx >> 9) & 1;
    int s    = (idx >> 10) & 7;
    int mat  = idx >> 13;
    int n = nt * 8 + (lane >> 2);
    int k = s * 16 + b * 8 + (lane & 3) * 2;
    const float* W = mat ? Wr : Wl;
    float w0 = W[k * DIM + n];
    float w1 = W[(k + 1) * DIM + n];
    g_bh[idx] = pack_hi(w0, w1);
    g_bl[idx] = pack_rn(trunc_res(w0), trunc_res(w1));
}

// ---------------------------------------------------------------------------
// Fused detect + zero.
__global__ void k_detect_zero(const unsigned int* __restrict__ w) {
    int i = blockIdx.x * blockDim.x + threadIdx.x;
    if (i < N_NODES) g_cnt[i] = 0;
    if (blockIdx.x == 0) {
        __shared__ unsigned int red[256];
        unsigned int v = w[2 * threadIdx.x + 1] | w[2 * (threadIdx.x + 256) + 1] |
                         w[2 * (threadIdx.x + 512) + 1] | w[2 * (threadIdx.x + 768) + 1];
        red[threadIdx.x] = v;
        __syncthreads();
        for (int s = 128; s > 0; s >>= 1) {
            if (threadIdx.x < s) red[threadIdx.x] |= red[threadIdx.x + s];
            __syncthreads();
        }
        if (threadIdx.x == 0) g_is64 = (red[0] == 0u) ? 1 : 0;
    }
}

__device__ __forceinline__ int edge_at(const int* __restrict__ ei, int pos, int is64) {
    return (is64 ? ei[2 * pos] : ei[pos]) & NODE_MASK;
}

__global__ void k_hist(const int* __restrict__ ei) {
    int i = blockIdx.x * blockDim.x + threadIdx.x;
    int is64 = g_is64;
    if (i < E_EDGES) {
        int d = edge_at(ei, E_EDGES + i, is64);
        atomicAdd(&g_cnt[d], 1);
    }
}

__global__ __launch_bounds__(1024) void k_scan() {
    __shared__ int part[1024];
    int tid  = threadIdx.x;
    int base = tid * 64;
    const int4* cp = (const int4*)(g_cnt + base);
    int sum = 0;
#pragma unroll
    for (int i = 0; i < 16; i++) {
        int4 c = cp[i];
        sum += c.x + c.y + c.z + c.w + 4;
    }
    part[tid] = sum;
    __syncthreads();
    for (int s = 1; s < 1024; s <<= 1) {
        int v = (tid >= s) ? part[tid - s] : 0;
        __syncthreads();
        part[tid] += v;
        __syncthreads();
    }
    int run = part[tid] - sum;
    int4* op = (int4*)(g_off + base);
    int4* up = (int4*)(g_cur + base);
#pragma unroll
    for (int i = 0; i < 16; i++) {
        int4 c = cp[i];
        int4 o;
        o.x = run; run += c.x + 1;
        o.y = run; run += c.y + 1;
        o.z = run; run += c.z + 1;
        o.w = run; run += c.w + 1;
        op[i] = o; up[i] = o;
    }
    if (tid == 1023) g_off[N_NODES] = run;
}

__global__ void k_scatter(const int* __restrict__ ei) {
    int i = blockIdx.x * blockDim.x + threadIdx.x;
    if (i >= TOT_EDGES) return;
    int is64 = g_is64;
    int s, d;
    if (i < E_EDGES) {
        s = edge_at(ei, i, is64);
        d = edge_at(ei, E_EDGES + i, is64);
    } else {
        s = d = i - E_EDGES;
    }
    int pos = atomicAdd(&g_cur[d], 1);
    g_srt[pos] = s;
}

// ---------------------------------------------------------------------------
// bf16-split tensor-core GEMM via mma.sync.m16n8k16 (sm_80+ PTX — compiles
// at plain sm_103, unlike tcgen05). D = xh*Wh + xl*Wh + xh*Wl, fp32 accum.
// Warp strip: 16 rows x 64 cols. No smem, no barriers.
__device__ __forceinline__ void mma16816(float* c, const uint32_t* a,
                                         uint32_t b0, uint32_t b1) {
    asm volatile(
        "mma.sync.aligned.m16n8k16.row.col.f32.bf16.bf16.f32 "
        "{%0,%1,%2,%3},{%4,%5,%6,%7},{%8,%9},{%0,%1,%2,%3};"
        : "+f"(c[0]), "+f"(c[1]), "+f"(c[2]), "+f"(c[3])
        : "r"(a[0]), "r"(a[1]), "r"(a[2]), "r"(a[3]), "r"(b0), "r"(b1));
}

__global__ __launch_bounds__(256) void k_gemm_mma(const float* __restrict__ x) {
    int tid  = threadIdx.x;
    int w    = tid >> 5;
    int lane = tid & 31;
    int g    = lane >> 2;           // 0..7
    int tg   = lane & 3;            // 0..3
    int mat  = blockIdx.y & 1;
    int ch   = blockIdx.y >> 1;     // column half: ntiles 0-7 or 8-15
    float* outp = mat ? g_xr : g_xl;
    int row0 = blockIdx.x * 128 + w * 16;
    int ntb  = ch * 8;

    const uint32_t* bhp = g_bh + mat * 8192;
    const uint32_t* blp = g_bl + mat * 8192;

    float acc[8][4];
#pragma unroll
    for (int t = 0; t < 8; t++)
#pragma unroll
        for (int j = 0; j < 4; j++) acc[t][j] = 0.f;

    const float* pa = x + (size_t)(row0 + g) * DIM + tg * 2;

#pragma unroll
    for (int s = 0; s < 8; s++) {
        int k0 = s * 16;
        // A fragment: rows g/g+8, cols k0 + tg*2 (+0/+8)
        float2 f0 = *(const float2*)(pa + k0);
        float2 f1 = *(const float2*)(pa + k0 + 8 * DIM);
        float2 f2 = *(const float2*)(pa + k0 + 8);
        float2 f3 = *(const float2*)(pa + k0 + 8 * DIM + 8);
        uint32_t ah[4], al[4];
        ah[0] = pack_hi(f0.x, f0.y);  al[0] = pack_rn(trunc_res(f0.x), trunc_res(f0.y));
        ah[1] = pack_hi(f1.x, f1.y);  al[1] = pack_rn(trunc_res(f1.x), trunc_res(f1.y));
        ah[2] = pack_hi(f2.x, f2.y);  al[2] = pack_rn(trunc_res(f2.x), trunc_res(f2.y));
        ah[3] = pack_hi(f3.x, f3.y);  al[3] = pack_rn(trunc_res(f3.x), trunc_res(f3.y));

        // B hi fragments: dense LDG.128 from fragment-packed array
        uint32_t b0[8], b1[8];
        {
            const uint32_t* p0 = bhp + ((s * 2 + 0) * 32 + lane) * 16 + ntb;
            const uint32_t* p1 = bhp + ((s * 2 + 1) * 32 + lane) * 16 + ntb;
            *(uint4*)&b0[0] = *(const uint4*)(p0);
            *(uint4*)&b0[4] = *(const uint4*)(p0 + 4);
            *(uint4*)&b1[0] = *(const uint4*)(p1);
            *(uint4*)&b1[4] = *(const uint4*)(p1 + 4);
        }
#pragma unroll
        for (int t = 0; t < 8; t++) {
            mma16816(acc[t], ah, b0[t], b1[t]);   // xh * Wh
            mma16816(acc[t], al, b0[t], b1[t]);   // xl * Wh
        }
        // B lo fragments (reuse registers)
        {
            const uint32_t* p0 = blp + ((s * 2 + 0) * 32 + lane) * 16 + ntb;
            const uint32_t* p1 = blp + ((s * 2 + 1) * 32 + lane) * 16 + ntb;
            *(uint4*)&b0[0] = *(const uint4*)(p0);
            *(uint4*)&b0[4] = *(const uint4*)(p0 + 4);
            *(uint4*)&b1[0] = *(const uint4*)(p1);
            *(uint4*)&b1[4] = *(const uint4*)(p1 + 4);
        }
#pragma unroll
        for (int t = 0; t < 8; t++)
            mma16816(acc[t], ah, b0[t], b1[t]);   // xh * Wl
    }

    // epilogue: c0,c1 -> row g, c2,c3 -> row g+8, cols (ntb+t)*8 + tg*2
    float* o0 = outp + (size_t)(row0 + g) * DIM + tg * 2;
    float* o1 = outp + (size_t)(row0 + g + 8) * DIM + tg * 2;
#pragma unroll
    for (int t = 0; t < 8; t++) {
        int col = (ntb + t) * 8;
        *(float2*)(o0 + col) = make_float2(acc[t][0], acc[t][1]);
        *(float2*)(o1 + col) = make_float2(acc[t][2], acc[t][3]);
    }
}

// ---------------------------------------------------------------------------
// Fused GATv2 attention + aggregation — R13 version verbatim (best measured).
#define NEG_SLOPE 0.2f
__device__ __forceinline__ float edge_score(float4 v, float4 xr4,
                                            float4 a06, float4 a04) {
    float zx = v.x + xr4.x, zy = v.y + xr4.y;
    float zz = v.z + xr4.z, zw = v.w + xr4.w;
    float t = fmaf(a06.x, zx, a04.x * fabsf(zx));
    t = fmaf(a06.y, zy, fmaf(a04.y, fabsf(zy), t));
    t = fmaf(a06.z, zz, fmaf(a04.z, fabsf(zz), t));
    t = fmaf(a06.w, zw, fmaf(a04.w, fabsf(zw), t));
    return t;
}
__device__ __forceinline__ float head_sum(float p) {
    p += __shfl_xor_sync(0xffffffffu, p, 1);
    p += __shfl_xor_sync(0xffffffffu, p, 2);
    p += __shfl_xor_sync(0xffffffffu, p, 4);
    p += __shfl_xor_sync(0xffffffffu, p, 8);
    return p;
}

__global__ __launch_bounds__(256) void k_attn(const float* __restrict__ att,
                                              const float* __restrict__ bias,
                                              float* __restrict__ out) {
    int gw   = (blockIdx.x * blockDim.x + threadIdx.x) >> 5;
    int lane = threadIdx.x & 31;
    if (gw >= N_NODES) return;

    const float4 xr4 = *(const float4*)(g_xr + (size_t)gw * DIM + lane * 4);
    const float4 a4  = *(const float4*)(att + lane * 4);
    float4 a06 = make_float4(0.6f * a4.x, 0.6f * a4.y, 0.6f * a4.z, 0.6f * a4.w);
    float4 a04 = make_float4(0.4f * a4.x, 0.4f * a4.y, 0.4f * a4.z, 0.4f * a4.w);

    int beg = g_off[gw];
    int end = g_off[gw + 1];

    float  den0 = 0.f, den1 = 0.f;
    float4 acc0 = make_float4(0.f, 0.f, 0.f, 0.f);
    float4 acc1 = make_float4(0.f, 0.f, 0.f, 0.f);

    int myidx = (beg + lane < end) ? g_srt[beg + lane] : 0;

    for (int base = beg; base < end; base += 32) {
        int nrem = end - base;
        int cnt  = nrem < 32 ? nrem : 32;
        int cur  = myidx;
        int nb = base + 32;
        myidx = (nb + lane < end) ? g_srt[nb + lane] : 0;

        int j = 0;
        for (; j + 4 <= cnt; j += 4) {
            int s0 = __shfl_sync(0xffffffffu, cur, j);
            int s1 = __shfl_sync(0xffffffffu, cur, j + 1);
            int s2 = __shfl_sync(0xffffffffu, cur, j + 2);
            int s3 = __shfl_sync(0xffffffffu, cur, j + 3);
            float4 v0 = *(const float4*)(g_xl + (size_t)s0 * DIM + lane * 4);
            float4 v1 = *(const float4*)(g_xl + (size_t)s1 * DIM + lane * 4);
            float4 v2 = *(const float4*)(g_xl + (size_t)s2 * DIM + lane * 4);
            float4 v3 = *(const float4*)(g_xl + (size_t)s3 * DIM + lane * 4);
            float p0 = head_sum(edge_score(v0, xr4, a06, a04));
            float p1 = head_sum(edge_score(v1, xr4, a06, a04));
            float p2 = head_sum(edge_score(v2, xr4, a06, a04));
            float p3 = head_sum(edge_score(v3, xr4, a06, a04));
            float w0 = __expf(p0), w1 = __expf(p1), w2 = __expf(p2), w3 = __expf(p3);
            den0 += w0 + w2;
            den1 += w1 + w3;
            acc0.x = fmaf(w0, v0.x, fmaf(w2, v2.x, acc0.x));
            acc0.y = fmaf(w0, v0.y, fmaf(w2, v2.y, acc0.y));
            acc0.z = fmaf(w0, v0.z, fmaf(w2, v2.z, acc0.z));
            acc0.w = fmaf(w0, v0.w, fmaf(w2, v2.w, acc0.w));
            acc1.x = fmaf(w1, v1.x, fmaf(w3, v3.x, acc1.x));
            acc1.y = fmaf(w1, v1.y, fmaf(w3, v3.y, acc1.y));
            acc1.z = fmaf(w1, v1.z, fmaf(w3, v3.z, acc1.z));
            acc1.w = fmaf(w1, v1.w, fmaf(w3, v3.w, acc1.w));
        }
        for (; j < cnt; j++) {
            int s = __shfl_sync(0xffffffffu, cur, j);
            float4 v = *(const float4*)(g_xl + (size_t)s * DIM + lane * 4);
            float w = __expf(head_sum(edge_score(v, xr4, a06, a04)));
            den0 += w;
            acc0.x = fmaf(w, v.x, acc0.x);
            acc0.y = fmaf(w, v.y, acc0.y);
            acc0.z = fmaf(w, v.z, acc0.z);
            acc0.w = fmaf(w, v.w, acc0.w);
        }
    }

    float inv = 1.f / (den0 + den1);
    float4 b4 = *(const float4*)(bias + lane * 4);
    float4 o;
    o.x = fmaf(acc0.x + acc1.x, inv, b4.x);
    o.y = fmaf(acc0.y + acc1.y, inv, b4.y);
    o.z = fmaf(acc0.z + acc1.z, inv, b4.z);
    o.w = fmaf(acc0.w + acc1.w, inv, b4.w);
    *(float4*)(out + (size_t)gw * DIM + lane * 4) = o;
}

// ---------------------------------------------------------------------------
extern "C" void kernel_launch(void* const* d_in, const int* in_sizes, int n_in,
                              void* d_out, int out_size) {
    const float* x    = 0;
    const int*   ei   = 0;
    const float* Wl   = 0;
    const float* Wr   = 0;
    const float* att  = 0;
    const float* bias = 0;
    for (int i = 0; i < n_in; i++) {
        int sz = in_sizes[i];
        if (sz == 8388608)                      x  = (const float*)d_in[i];
        else if (sz == 2097152 || sz == 4194304) ei = (const int*)d_in[i];
        else if (sz == 16384) { if (!Wl) Wl = (const float*)d_in[i]; else Wr = (const float*)d_in[i]; }
        else if (sz == 128)   { if (!att) att = (const float*)d_in[i]; else bias = (const float*)d_in[i]; }
    }
    float* out = (float*)d_out;

    // k_gemm_mma at launch index 3 — the slot ncu captures.
    k_prep<<<64, 256>>>(Wl, Wr);                                     // 0
    k_detect_zero<<<N_NODES / 256, 256>>>((const unsigned int*)ei);  // 1
    k_hist<<<E_EDGES / 256, 256>>>(ei);                              // 2
    k_gemm_mma<<<dim3(512, 4), 256>>>(x);                            // 3  <- profiled
    k_scan<<<1, 1024>>>();                                           // 4
    k_scatter<<<(TOT_EDGES + 255) / 256, 256>>>(ei);                 // 5
    k_attn<<<(N_NODES * 32) / 256, 256>>>(att, bias, out);           // 6
}